// round 5
// baseline (speedup 1.0000x reference)
#include <cuda_runtime.h>

// Problem-fixed shapes: B=4, C=256, Ch=128, H=W=64 -> N=4096
#define NPIX 4096

// ---------------- scratch (no allocations allowed -> __device__ global) ----
// layout (float offsets):
//   T   : temp f1/g1      4*128*4096 = 2097152
//   F   : f               2097152
//   G   : g               2097152
//   H   : h               4*256*4096 = 4194304
//   PM  : partial max     4*32*4096  = 524288
//   PS  : partial sum     524288
//   FM  : final max       4*4096     = 16384
//   FS  : final 1/sum     16384
#define OFF_T  0
#define OFF_F  2097152
#define OFF_G  4194304
#define OFF_H  6291456
#define OFF_PM 10485760
#define OFF_PS 11010048
#define OFF_FM 11534336
#define OFF_FS 11550720
#define SCRATCH_FLOATS 11567104

static __device__ float g_scratch[SCRATCH_FLOATS];

// ---------------------------------------------------------------------------
// Generic row-major GEMM:  C[M x 4096] = epilogue( A[M x K] @ X[K x 4096] )
//   MODE 0: relu(acc + bias)
//   MODE 1: acc + bias
//   MODE 2: gamma*acc + residual   (used for final output, A is per-batch h)
// 128x128 tile, BK=8, 256 threads, 8x8 per thread.
// A per-batch stride = aStride (0 for shared weights), X stride = K*4096,
// C / residual stride = M*4096.
// ---------------------------------------------------------------------------
template <int MODE>
__global__ __launch_bounds__(256, 2)
void gemm_rm(const float* __restrict__ A, size_t aStride,
             const float* __restrict__ Xall,
             const float* __restrict__ bias,
             const float* __restrict__ resAll,
             const float* __restrict__ gamma,
             float* __restrict__ Call,
             int M, int K)
{
    const float* Ab = A + (size_t)blockIdx.z * aStride;
    const float* X  = Xall + (size_t)blockIdx.z * (size_t)K * NPIX;
    float*       Cb = Call + (size_t)blockIdx.z * (size_t)M * NPIX;

    const int m0 = blockIdx.y * 128;
    const int n0 = blockIdx.x * 128;

    __shared__ float As[8][128];
    __shared__ float Bs[8][128];

    const int t    = threadIdx.x;
    const int ty   = t >> 4;          // 0..15
    const int tx   = t & 15;          // 0..15
    const int arow = t >> 1;          // 0..127
    const int aseg = (t & 1) * 4;     // 0 or 4
    const int brow = t >> 5;          // 0..7
    const int bcol = (t & 31) * 4;    // 0..124

    float acc[8][8];
#pragma unroll
    for (int i = 0; i < 8; i++)
#pragma unroll
        for (int j = 0; j < 8; j++) acc[i][j] = 0.0f;

    for (int k0 = 0; k0 < K; k0 += 8) {
        float4 av = *(const float4*)(Ab + (size_t)(m0 + arow) * K + k0 + aseg);
        float4 bv = *(const float4*)(X + (size_t)(k0 + brow) * NPIX + n0 + bcol);
        __syncthreads();
        As[aseg + 0][arow] = av.x;
        As[aseg + 1][arow] = av.y;
        As[aseg + 2][arow] = av.z;
        As[aseg + 3][arow] = av.w;
        *(float4*)(&Bs[brow][bcol]) = bv;
        __syncthreads();
#pragma unroll
        for (int k = 0; k < 8; k++) {
            float a[8], b[8];
#pragma unroll
            for (int i = 0; i < 8; i++) a[i] = As[k][ty * 8 + i];
#pragma unroll
            for (int j = 0; j < 8; j++) b[j] = Bs[k][tx * 8 + j];
#pragma unroll
            for (int i = 0; i < 8; i++)
#pragma unroll
                for (int j = 0; j < 8; j++)
                    acc[i][j] = fmaf(a[i], b[j], acc[i][j]);
        }
    }

    if (MODE == 2) {
        const float gm = *gamma;
        const float* Rb = resAll + (size_t)blockIdx.z * (size_t)M * NPIX;
#pragma unroll
        for (int i = 0; i < 8; i++) {
            const int m = m0 + ty * 8 + i;
            const float* xr = Rb + (size_t)m * NPIX + n0 + tx * 8;
            float* cp = Cb + (size_t)m * NPIX + n0 + tx * 8;
#pragma unroll
            for (int j = 0; j < 8; j++) cp[j] = fmaf(gm, acc[i][j], xr[j]);
        }
    } else {
#pragma unroll
        for (int i = 0; i < 8; i++) {
            const int m = m0 + ty * 8 + i;
            const float bvv = bias[m];
            float* cp = Cb + (size_t)m * NPIX + n0 + tx * 8;
#pragma unroll
            for (int j = 0; j < 8; j++) {
                float v = acc[i][j] + bvv;
                if (MODE == 0) v = fmaxf(v, 0.0f);
                cp[j] = v;
            }
        }
    }
}

// ---------------------------------------------------------------------------
// attn[n][m] = sum_c f[c][n] * g[c][m]    (K = 128), per batch.
// Both operands are K-major (row = channel), tiles load contiguously.
// Writes raw logits directly into d_out's attn region.
// ---------------------------------------------------------------------------
__global__ __launch_bounds__(256, 2)
void gemm_attn(const float* __restrict__ F, const float* __restrict__ G,
               float* __restrict__ attnAll)
{
    const int K = 128;
    const float* f = F + (size_t)blockIdx.z * K * NPIX;
    const float* g = G + (size_t)blockIdx.z * K * NPIX;
    float* Aout = attnAll + (size_t)blockIdx.z * (size_t)NPIX * NPIX;

    const int n0 = blockIdx.y * 128;
    const int m0 = blockIdx.x * 128;

    __shared__ float As[8][128];
    __shared__ float Bs[8][128];

    const int t  = threadIdx.x;
    const int ty = t >> 4;
    const int tx = t & 15;
    const int r  = t >> 5;          // 0..7
    const int c4 = (t & 31) * 4;    // 0..124

    float acc[8][8];
#pragma unroll
    for (int i = 0; i < 8; i++)
#pragma unroll
        for (int j = 0; j < 8; j++) acc[i][j] = 0.0f;

    for (int k0 = 0; k0 < K; k0 += 8) {
        float4 av = *(const float4*)(f + (size_t)(k0 + r) * NPIX + n0 + c4);
        float4 bv = *(const float4*)(g + (size_t)(k0 + r) * NPIX + m0 + c4);
        __syncthreads();
        *(float4*)(&As[r][c4]) = av;
        *(float4*)(&Bs[r][c4]) = bv;
        __syncthreads();
#pragma unroll
        for (int k = 0; k < 8; k++) {
            float a[8], b[8];
#pragma unroll
            for (int i = 0; i < 8; i++) a[i] = As[k][ty * 8 + i];
#pragma unroll
            for (int j = 0; j < 8; j++) b[j] = Bs[k][tx * 8 + j];
#pragma unroll
            for (int i = 0; i < 8; i++)
#pragma unroll
                for (int j = 0; j < 8; j++)
                    acc[i][j] = fmaf(a[i], b[j], acc[i][j]);
        }
    }

#pragma unroll
    for (int i = 0; i < 8; i++) {
        float* cp = Aout + (size_t)(n0 + ty * 8 + i) * NPIX + m0 + tx * 8;
#pragma unroll
        for (int j = 0; j < 8; j++) cp[j] = acc[i][j];
    }
}

// ---------------------------------------------------------------------------
// Softmax over axis n (rows) for each column m of attn[b][n][m], 3 phases.
// Column index m is contiguous -> coalesced across threads at every n.
// ---------------------------------------------------------------------------
__global__ void softmax_part(const float* __restrict__ attnAll)
{
    // grid (16, 32, 4), 256 threads: block = (m-chunk of 256, n-chunk of 128, b)
    const int m  = blockIdx.x * 256 + threadIdx.x;
    const int b  = blockIdx.z;
    const int ns = blockIdx.y;
    const float* p = attnAll + (size_t)b * NPIX * NPIX + (size_t)ns * 128 * NPIX + m;

    float mx = -3.402823466e38f, sm = 0.0f;
    for (int n = 0; n < 128; n++) {
        float v  = p[(size_t)n * NPIX];
        float nm = fmaxf(mx, v);
        sm = sm * __expf(mx - nm) + __expf(v - nm);
        mx = nm;
    }
    g_scratch[OFF_PM + ((size_t)b * 32 + ns) * NPIX + m] = mx;
    g_scratch[OFF_PS + ((size_t)b * 32 + ns) * NPIX + m] = sm;
}

__global__ void softmax_comb()
{
    // grid (16, 4), 256 threads
    const int m = blockIdx.x * 256 + threadIdx.x;
    const int b = blockIdx.y;
    float mx = -3.402823466e38f, sm = 0.0f;
    for (int s = 0; s < 32; s++) {
        float pm = g_scratch[OFF_PM + ((size_t)b * 32 + s) * NPIX + m];
        float ps = g_scratch[OFF_PS + ((size_t)b * 32 + s) * NPIX + m];
        float nm = fmaxf(mx, pm);
        sm = sm * __expf(mx - nm) + ps * __expf(pm - nm);
        mx = nm;
    }
    g_scratch[OFF_FM + (size_t)b * NPIX + m] = mx;
    g_scratch[OFF_FS + (size_t)b * NPIX + m] = 1.0f / sm;
}

__global__ void softmax_norm(float* __restrict__ attnAll)
{
    // grid (16, 32, 4), 256 threads
    const int m  = blockIdx.x * 256 + threadIdx.x;
    const int b  = blockIdx.z;
    const int ns = blockIdx.y;
    const float mx  = g_scratch[OFF_FM + (size_t)b * NPIX + m];
    const float inv = g_scratch[OFF_FS + (size_t)b * NPIX + m];
    float* p = attnAll + (size_t)b * NPIX * NPIX + (size_t)ns * 128 * NPIX + m;
#pragma unroll 4
    for (int n = 0; n < 128; n++) {
        float v = p[(size_t)n * NPIX];
        p[(size_t)n * NPIX] = __expf(v - mx) * inv;
    }
}

// ---------------------------------------------------------------------------
extern "C" void kernel_launch(void* const* d_in, const int* in_sizes, int n_in,
                              void* d_out, int out_size)
{
    (void)in_sizes; (void)n_in; (void)out_size;

    const float* x     = (const float*)d_in[0];
    const float* wf1   = (const float*)d_in[1];
    const float* bf1   = (const float*)d_in[2];
    const float* wf2   = (const float*)d_in[3];
    const float* bf2   = (const float*)d_in[4];
    const float* wg1   = (const float*)d_in[5];
    const float* bg1   = (const float*)d_in[6];
    const float* wg2   = (const float*)d_in[7];
    const float* bg2   = (const float*)d_in[8];
    const float* wh    = (const float*)d_in[9];
    const float* bh    = (const float*)d_in[10];
    const float* gamma = (const float*)d_in[11];

    float* out  = (float*)d_out;                       // (B, C, H, W) = 4*256*4096
    float* attn = out + (size_t)4 * 256 * NPIX;        // (B, N, N)    = 4*4096*4096

    float* scratch = nullptr;
    cudaGetSymbolAddress((void**)&scratch, g_scratch);
    float* tbuf = scratch + OFF_T;
    float* fbuf = scratch + OFF_F;
    float* gbuf = scratch + OFF_G;
    float* hbuf = scratch + OFF_H;

    dim3 blk(256);

    // projections (batched over z=4)
    gemm_rm<0><<<dim3(32, 1, 4), blk>>>(wf1, 0, x,    bf1, nullptr, nullptr, tbuf, 128, 256);
    gemm_rm<1><<<dim3(32, 1, 4), blk>>>(wf2, 0, tbuf, bf2, nullptr, nullptr, fbuf, 128, 128);
    gemm_rm<0><<<dim3(32, 1, 4), blk>>>(wg1, 0, x,    bg1, nullptr, nullptr, tbuf, 128, 256);
    gemm_rm<1><<<dim3(32, 1, 4), blk>>>(wg2, 0, tbuf, bg2, nullptr, nullptr, gbuf, 128, 128);
    gemm_rm<1><<<dim3(32, 2, 4), blk>>>(wh,  0, x,    bh,  nullptr, nullptr, hbuf, 256, 256);

    // attn logits straight into the output buffer
    gemm_attn<<<dim3(32, 32, 4), blk>>>(fbuf, gbuf, attn);

    // softmax over axis n, in-place on d_out's attn region
    softmax_part<<<dim3(16, 32, 4), blk>>>(attn);
    softmax_comb<<<dim3(16, 4), blk>>>();
    softmax_norm<<<dim3(16, 32, 4), blk>>>(attn);

    // out = gamma * (h @ attn_soft) + x
    gemm_rm<2><<<dim3(32, 2, 4), blk>>>(hbuf, (size_t)256 * NPIX, attn,
                                        nullptr, x, gamma, out, 256, 4096);
}

// round 7
// speedup vs baseline: 3.1282x; 3.1282x over previous
#include <cuda_runtime.h>

// Problem-fixed shapes: B=4, C=256, Ch=128, H=W=64 -> N=4096
#define NPIX 4096

// ---------------- scratch (no allocations allowed -> __device__ global) ----
#define OFF_T  0
#define OFF_F  2097152
#define OFF_G  4194304
#define OFF_H  6291456
#define OFF_PM 10485760
#define OFF_PS 11010048
#define OFF_FM 11534336
#define OFF_FS 11550720
#define SCRATCH_FLOATS 11567104

static __device__ float g_scratch[SCRATCH_FLOATS];

// ---------------------------------------------------------------------------
// tf32 helpers
// ---------------------------------------------------------------------------
__device__ __forceinline__ unsigned f2tf32(float x) {
    unsigned r;
    asm("cvt.rna.tf32.f32 %0, %1;" : "=r"(r) : "f"(x));
    return r;
}

#define MMA_TF32(c, a, b)                                                    \
    asm volatile(                                                            \
        "mma.sync.aligned.m16n8k8.row.col.f32.tf32.tf32.f32 "                \
        "{%0,%1,%2,%3},{%4,%5,%6,%7},{%8,%9},{%0,%1,%2,%3};"                 \
        : "+f"(c[0]), "+f"(c[1]), "+f"(c[2]), "+f"(c[3])                     \
        : "r"(a[0]), "r"(a[1]), "r"(a[2]), "r"(a[3]), "r"(b[0]), "r"(b[1]))

// ---------------------------------------------------------------------------
// Tensor-core GEMM:  C[M x 4096] = epi( A[M x K] @ X[K x 4096] )
//   A_COLMAJOR=0: A[m][k] at Ab[m*lda + k]   (weights / h)
//   A_COLMAJOR=1: A[m][k] at Ab[k*lda + m]   (f, k-major)
//   SPLIT=3: 3xTF32 error-compensated path (fp32-grade accuracy)
//   SPLIT=1: single tf32
//   MODE 0: relu(acc+bias)  1: acc+bias  2: gamma*acc+residual  3: raw store
// Block: 128x128 tile, BK=16, 256 threads = 8 warps (2 m x 4 n), each warp
// 64x32 via 4x4 grid of m16n8k8 mma tiles.
// ---------------------------------------------------------------------------
template <int A_COLMAJOR, int SPLIT, int MODE>
__global__ __launch_bounds__(256)
void mma_gemm(const float* __restrict__ A, size_t aStride, int lda,
              const float* __restrict__ X, size_t xStride,
              const float* __restrict__ bias,
              const float* __restrict__ resAll,
              const float* __restrict__ gamma,
              float* __restrict__ C, size_t cStride,
              int K)
{
    constexpr int BK = 16;
    constexpr int LDSW = 136;   // 128 + 8 pad -> conflict-free frag reads

    __shared__ float Ah[BK][LDSW];
    __shared__ float Bh[BK][LDSW];
    __shared__ float Al[BK][LDSW];
    __shared__ float Bl[BK][LDSW];

    const float* Ab = A + (size_t)blockIdx.z * aStride;
    const float* Xb = X + (size_t)blockIdx.z * xStride;
    float*       Cb = C + (size_t)blockIdx.z * cStride;

    const int m0   = blockIdx.y * 128;
    const int n0   = blockIdx.x * 128;
    const int t    = threadIdx.x;
    const int lane = t & 31;
    const int warp = t >> 5;
    const int wm   = (warp >> 2) * 64;   // warp m-offset (2 warps)
    const int wn   = (warp & 3) * 32;    // warp n-offset (4 warps)
    const int gid  = lane >> 2;          // groupID 0..7
    const int tig  = lane & 3;           // thread-in-group 0..3

    float acc[4][4][4];
#pragma unroll
    for (int mt = 0; mt < 4; mt++)
#pragma unroll
        for (int nt = 0; nt < 4; nt++)
#pragma unroll
            for (int r = 0; r < 4; r++) acc[mt][nt][r] = 0.0f;

    for (int k0 = 0; k0 < K; k0 += BK) {
        __syncthreads();
        // ---- load B tile (always row-major K x 4096) ----
#pragma unroll
        for (int i = 0; i < 2; i++) {
            int id = t + 256 * i;
            int r  = id >> 5;
            int c  = (id & 31) * 4;
            float4 v = *(const float4*)(Xb + (size_t)(k0 + r) * NPIX + n0 + c);
            float4 hv;
            hv.x = __uint_as_float(f2tf32(v.x));
            hv.y = __uint_as_float(f2tf32(v.y));
            hv.z = __uint_as_float(f2tf32(v.z));
            hv.w = __uint_as_float(f2tf32(v.w));
            *(float4*)(&Bh[r][c]) = hv;
            if (SPLIT == 3) {
                float4 lv;
                lv.x = __uint_as_float(f2tf32(v.x - hv.x));
                lv.y = __uint_as_float(f2tf32(v.y - hv.y));
                lv.z = __uint_as_float(f2tf32(v.z - hv.z));
                lv.w = __uint_as_float(f2tf32(v.w - hv.w));
                *(float4*)(&Bl[r][c]) = lv;
            }
        }
        // ---- load A tile ----
        if (A_COLMAJOR) {
#pragma unroll
            for (int i = 0; i < 2; i++) {
                int id = t + 256 * i;
                int r  = id >> 5;
                int c  = (id & 31) * 4;
                float4 v = *(const float4*)(Ab + (size_t)(k0 + r) * lda + m0 + c);
                float4 hv;
                hv.x = __uint_as_float(f2tf32(v.x));
                hv.y = __uint_as_float(f2tf32(v.y));
                hv.z = __uint_as_float(f2tf32(v.z));
                hv.w = __uint_as_float(f2tf32(v.w));
                *(float4*)(&Ah[r][c]) = hv;
                if (SPLIT == 3) {
                    float4 lv;
                    lv.x = __uint_as_float(f2tf32(v.x - hv.x));
                    lv.y = __uint_as_float(f2tf32(v.y - hv.y));
                    lv.z = __uint_as_float(f2tf32(v.z - hv.z));
                    lv.w = __uint_as_float(f2tf32(v.w - hv.w));
                    *(float4*)(&Al[r][c]) = lv;
                }
            }
        } else {
#pragma unroll
            for (int i = 0; i < 2; i++) {
                int id = t + 256 * i;
                int m  = id >> 2;
                int ks = (id & 3) * 4;
                float4 v = *(const float4*)(Ab + (size_t)(m0 + m) * lda + k0 + ks);
                float h0 = __uint_as_float(f2tf32(v.x));
                float h1 = __uint_as_float(f2tf32(v.y));
                float h2 = __uint_as_float(f2tf32(v.z));
                float h3 = __uint_as_float(f2tf32(v.w));
                Ah[ks + 0][m] = h0;
                Ah[ks + 1][m] = h1;
                Ah[ks + 2][m] = h2;
                Ah[ks + 3][m] = h3;
                if (SPLIT == 3) {
                    Al[ks + 0][m] = __uint_as_float(f2tf32(v.x - h0));
                    Al[ks + 1][m] = __uint_as_float(f2tf32(v.y - h1));
                    Al[ks + 2][m] = __uint_as_float(f2tf32(v.z - h2));
                    Al[ks + 3][m] = __uint_as_float(f2tf32(v.w - h3));
                }
            }
        }
        __syncthreads();

        // ---- MMA over the BK tile, 2 k-steps of 8 ----
#pragma unroll
        for (int ks = 0; ks < BK; ks += 8) {
            unsigned bh[4][2], bl[4][2];
#pragma unroll
            for (int nt = 0; nt < 4; nt++) {
                int col = wn + nt * 8 + gid;
                bh[nt][0] = __float_as_uint(Bh[ks + tig][col]);
                bh[nt][1] = __float_as_uint(Bh[ks + 4 + tig][col]);
                if (SPLIT == 3) {
                    bl[nt][0] = __float_as_uint(Bl[ks + tig][col]);
                    bl[nt][1] = __float_as_uint(Bl[ks + 4 + tig][col]);
                }
            }
#pragma unroll
            for (int mt = 0; mt < 4; mt++) {
                int rowm = wm + mt * 16 + gid;
                unsigned ah[4], al[4];
                ah[0] = __float_as_uint(Ah[ks + tig][rowm]);
                ah[1] = __float_as_uint(Ah[ks + tig][rowm + 8]);
                ah[2] = __float_as_uint(Ah[ks + 4 + tig][rowm]);
                ah[3] = __float_as_uint(Ah[ks + 4 + tig][rowm + 8]);
                if (SPLIT == 3) {
                    al[0] = __float_as_uint(Al[ks + tig][rowm]);
                    al[1] = __float_as_uint(Al[ks + tig][rowm + 8]);
                    al[2] = __float_as_uint(Al[ks + 4 + tig][rowm]);
                    al[3] = __float_as_uint(Al[ks + 4 + tig][rowm + 8]);
                }
#pragma unroll
                for (int nt = 0; nt < 4; nt++) {
                    if (SPLIT == 3) {
                        MMA_TF32(acc[mt][nt], al, bh[nt]);
                        MMA_TF32(acc[mt][nt], ah, bl[nt]);
                    }
                    MMA_TF32(acc[mt][nt], ah, bh[nt]);
                }
            }
        }
    }

    // ---- epilogue ----
    const float gm = (MODE == 2) ? *gamma : 0.0f;
#pragma unroll
    for (int mt = 0; mt < 4; mt++) {
#pragma unroll
        for (int half = 0; half < 2; half++) {
            const int m = m0 + wm + mt * 16 + gid + half * 8;
            float bv = 0.0f;
            if (MODE == 0 || MODE == 1) bv = bias[m];
#pragma unroll
            for (int nt = 0; nt < 4; nt++) {
                const int col = n0 + wn + nt * 8 + tig * 2;
                float v0 = acc[mt][nt][half * 2 + 0];
                float v1 = acc[mt][nt][half * 2 + 1];
                if (MODE == 0) {
                    v0 = fmaxf(v0 + bv, 0.0f);
                    v1 = fmaxf(v1 + bv, 0.0f);
                } else if (MODE == 1) {
                    v0 += bv;
                    v1 += bv;
                } else if (MODE == 2) {
                    const float* rp = resAll + (size_t)blockIdx.z * cStride +
                                      (size_t)m * NPIX + col;
                    v0 = fmaf(gm, v0, rp[0]);
                    v1 = fmaf(gm, v1, rp[1]);
                }
                *(float2*)(Cb + (size_t)m * NPIX + col) = make_float2(v0, v1);
            }
        }
    }
}

// ---------------------------------------------------------------------------
// Softmax over axis n (rows) for each column m of attn[b][n][m], 3 phases.
// ---------------------------------------------------------------------------
__global__ void softmax_part(const float* __restrict__ attnAll)
{
    const int m  = blockIdx.x * 256 + threadIdx.x;
    const int b  = blockIdx.z;
    const int ns = blockIdx.y;
    const float* p = attnAll + (size_t)b * NPIX * NPIX + (size_t)ns * 128 * NPIX + m;

    float mx = -3.402823466e38f, sm = 0.0f;
    for (int n = 0; n < 128; n++) {
        float v  = p[(size_t)n * NPIX];
        float nm = fmaxf(mx, v);
        sm = sm * __expf(mx - nm) + __expf(v - nm);
        mx = nm;
    }
    g_scratch[OFF_PM + ((size_t)b * 32 + ns) * NPIX + m] = mx;
    g_scratch[OFF_PS + ((size_t)b * 32 + ns) * NPIX + m] = sm;
}

__global__ void softmax_comb()
{
    const int m = blockIdx.x * 256 + threadIdx.x;
    const int b = blockIdx.y;
    float mx = -3.402823466e38f, sm = 0.0f;
    for (int s = 0; s < 32; s++) {
        float pm = g_scratch[OFF_PM + ((size_t)b * 32 + s) * NPIX + m];
        float ps = g_scratch[OFF_PS + ((size_t)b * 32 + s) * NPIX + m];
        float nm = fmaxf(mx, pm);
        sm = sm * __expf(mx - nm) + ps * __expf(pm - nm);
        mx = nm;
    }
    g_scratch[OFF_FM + (size_t)b * NPIX + m] = mx;
    g_scratch[OFF_FS + (size_t)b * NPIX + m] = 1.0f / sm;
}

__global__ void softmax_norm(float* __restrict__ attnAll)
{
    const int m  = blockIdx.x * 256 + threadIdx.x;
    const int b  = blockIdx.z;
    const int ns = blockIdx.y;
    const float mx  = g_scratch[OFF_FM + (size_t)b * NPIX + m];
    const float inv = g_scratch[OFF_FS + (size_t)b * NPIX + m];
    float* p = attnAll + (size_t)b * NPIX * NPIX + (size_t)ns * 128 * NPIX + m;
#pragma unroll 4
    for (int n = 0; n < 128; n++) {
        float v = p[(size_t)n * NPIX];
        p[(size_t)n * NPIX] = __expf(v - mx) * inv;
    }
}

// ---------------------------------------------------------------------------
extern "C" void kernel_launch(void* const* d_in, const int* in_sizes, int n_in,
                              void* d_out, int out_size)
{
    (void)in_sizes; (void)n_in; (void)out_size;

    const float* x     = (const float*)d_in[0];
    const float* wf1   = (const float*)d_in[1];
    const float* bf1   = (const float*)d_in[2];
    const float* wf2   = (const float*)d_in[3];
    const float* bf2   = (const float*)d_in[4];
    const float* wg1   = (const float*)d_in[5];
    const float* bg1   = (const float*)d_in[6];
    const float* wg2   = (const float*)d_in[7];
    const float* bg2   = (const float*)d_in[8];
    const float* wh    = (const float*)d_in[9];
    const float* bh    = (const float*)d_in[10];
    const float* gamma = (const float*)d_in[11];

    float* out  = (float*)d_out;                       // (B, C, H, W)
    float* attn = out + (size_t)4 * 256 * NPIX;        // (B, N, N)

    float* scratch = nullptr;
    cudaGetSymbolAddress((void**)&scratch, g_scratch);
    float* tbuf = scratch + OFF_T;
    float* fbuf = scratch + OFF_F;
    float* gbuf = scratch + OFF_G;
    float* hbuf = scratch + OFF_H;

    dim3 blk(256);
    const size_t sX  = (size_t)256 * NPIX;   // x / h batch stride
    const size_t sCh = (size_t)128 * NPIX;   // half-channel batch stride
    const size_t sAt = (size_t)NPIX * NPIX;  // attn batch stride

    // projections (accuracy-critical f/g path uses 3xTF32)
    mma_gemm<0, 3, 0><<<dim3(32, 1, 4), blk>>>(wf1, 0, 256, x, sX,
                                               bf1, nullptr, nullptr, tbuf, sCh, 256);
    mma_gemm<0, 3, 1><<<dim3(32, 1, 4), blk>>>(wf2, 0, 128, tbuf, sCh,
                                               bf2, nullptr, nullptr, fbuf, sCh, 128);
    mma_gemm<0, 3, 0><<<dim3(32, 1, 4), blk>>>(wg1, 0, 256, x, sX,
                                               bg1, nullptr, nullptr, tbuf, sCh, 256);
    mma_gemm<0, 3, 1><<<dim3(32, 1, 4), blk>>>(wg2, 0, 128, tbuf, sCh,
                                               bg2, nullptr, nullptr, gbuf, sCh, 128);
    mma_gemm<0, 1, 1><<<dim3(32, 2, 4), blk>>>(wh, 0, 256, x, sX,
                                               bh, nullptr, nullptr, hbuf, sX, 256);

    // attn logits = f^T g (3xTF32), straight into d_out's attn region
    mma_gemm<1, 3, 3><<<dim3(32, 32, 4), blk>>>(fbuf, sCh, NPIX, gbuf, sCh,
                                                nullptr, nullptr, nullptr,
                                                attn, sAt, 128);

    // softmax over axis n, in-place
    softmax_part<<<dim3(16, 32, 4), blk>>>(attn);
    softmax_comb<<<dim3(16, 4), blk>>>();
    softmax_norm<<<dim3(16, 32, 4), blk>>>(attn);

    // out = gamma * (h @ attn_soft) + x   (single tf32: residual dominates)
    mma_gemm<0, 1, 2><<<dim3(32, 2, 4), blk>>>(hbuf, sX, NPIX, attn, sAt,
                                               nullptr, x, gamma, out, sX, 4096);
}